// round 14
// baseline (speedup 1.0000x reference)
#include <cuda_runtime.h>
#include <math.h>

// Problem dims
#define Bz 64
#define Sz 1024
#define Dz 64
#define Hz 512
#define Az 16

// Persistent kernel config
#define NBLK 128
#define NTHR 512
#define PITCH 644                    // smem act row pitch in floats (%32==4 -> conflict-free LDS.128)

// smem layout (floats)
#define ACT_OFF 0
#define W1S_OFF (32 * PITCH)                 // gate weights [warp][gate][640]  (15360 f)
#define W2S_OFF (W1S_OFF + 3 * 8 * 640)      // cb_w1 slice  [warp][512]        (4096 f)
#define W3S_OFF (W2S_OFF + 8 * 512)          // cb_w2 slice  [d][8]             (512 f)
#define AS_OFF  (W3S_OFF + 512)              // a_s[8][32]                      (256 f)
#define PART_OFF (AS_OFF + 256)              // partials: 16 warps x 32 lanes x float4 (2048 f)
#define SMEM_FLOATS (PART_OFF + 2048)
#define SMEM_BYTES (SMEM_FLOATS * 4)         // 171,520 B (< 227KB/block)

// d_out layout: q [B,S,A] | cb_preds [B,S,D] | hidden [B,H] | ca1_out [B,S,H]
#define QOFF   0
#define CBOFF  (Bz * Sz * Az)
#define HIDOFF (CBOFF + Bz * Sz * Dz)
#define CA1OFF (HIDOFF + Bz * Hz)

// ---------------- device scratch (static __device__ only; no allocs) ----------------
__device__ float g_outs[Sz * Bz * Hz];   // h_t for all t, layout [t][b][j]
__device__ float g_wpack[3 * Hz * 640];  // packed gate weights [gate][k][j]; j: 0..511=h, 512..575=x, 576..639=pred
__device__ float g_bsum[2 * Hz];         // b_ih+b_hh for r,z gates
__device__ float g_bin[Hz];              // b_ih for n gate
__device__ float g_bhn[Hz];              // b_hh for n gate
__device__ float g_pred[2][Bz * Dz];     // parity-double-buffered pred accumulators [b][d]
__device__ unsigned long long g_barh[64];  // per-half barrier counters at [0] and [32]
__device__ unsigned long long g_bar_init;  // one-shot full-grid barrier

__global__ void reset_kernel() {
    int idx = blockIdx.x * blockDim.x + threadIdx.x;
    if (idx < 2 * Bz * Dz) ((float*)g_pred)[idx] = 0.0f;
    if (idx < 64) g_barh[idx] = 0ULL;
    if (idx == 64) g_bar_init = 0ULL;
}

// No-op launch-slot shifters so ncu (-s 5 -c 1) lands on recur_kernel.
__global__ void noop_a_kernel() {}
__global__ void noop_b_kernel() {}

__device__ __forceinline__ float4 ldcg4(const float4* p) { return __ldcg(p); }

// ---------------- packed f32x2 helpers ----------------
typedef unsigned long long u64;

__device__ __forceinline__ u64 pk2(float lo, float hi) {
    u64 r;
    asm("mov.b64 %0, {%1, %2};" : "=l"(r) : "f"(lo), "f"(hi));
    return r;
}
__device__ __forceinline__ void upk2(u64 v, float& lo, float& hi) {
    asm("mov.b64 {%0, %1}, %2;" : "=f"(lo), "=f"(hi) : "l"(v));
}
__device__ __forceinline__ void fma2(u64& acc, u64 a, u64 b) {
    asm("fma.rn.f32x2 %0, %1, %2, %3;" : "=l"(acc) : "l"(a), "l"(b), "l"(acc));
}
__device__ __forceinline__ float red2(u64 a, u64 b) {
    float l0, h0, l1, h1;
    upk2(a, l0, h0); upk2(b, l1, h1);
    return (l0 + h0) + (l1 + h1);
}

// Per-half grid barrier (64 CTAs per half, all co-resident).
__device__ __forceinline__ void gsync_half(int half, unsigned long long& target) {
    __syncthreads();
    if (threadIdx.x == 0) {
        __threadfence();
        target += 64ULL;
        atomicAdd(&g_barh[half * 32], 1ULL);
        while (*(volatile unsigned long long*)&g_barh[half * 32] < target) { }
        __threadfence();
    }
    __syncthreads();
}

__device__ __forceinline__ void fma4(float& acc, const float4 va, const float4 vb) {
    acc = fmaf(va.x, vb.x, acc);
    acc = fmaf(va.y, vb.y, acc);
    acc = fmaf(va.z, vb.z, acc);
    acc = fmaf(va.w, vb.w, acc);
}

__device__ __forceinline__ float sigmoidf_(float v) { return 1.0f / (1.0f + expf(-v)); }

// =====================================================================================
// Persistent recurrent kernel: 512 threads (16 warps = 4/SMSP), smem weights.
// Warp w (w<8) and partner w+8 j-split each k's dot products; partials combined
// through smem by warps 0-7. All weight reads are 1-wavefront smem broadcasts.
// =====================================================================================
__global__ void __launch_bounds__(NTHR, 1) recur_kernel(
    const float* __restrict__ x,      // [B,S,D]
    const float* __restrict__ W_ih,   // [3H, 2D]
    const float* __restrict__ W_hh,   // [3H, H]
    const float* __restrict__ b_ih,   // [3H]
    const float* __restrict__ b_hh,   // [3H]
    const float* __restrict__ cb_w1,  // [H,H]
    const float* __restrict__ cb_b1,  // [H]
    const float* __restrict__ cb_w2,  // [D,H]
    const float* __restrict__ cb_b2,  // [D]
    float* __restrict__ out_cb,       // d_out + CBOFF  [B,S,D]
    float* __restrict__ out_hid)      // d_out + HIDOFF [B,H]
{
    extern __shared__ float sh[];
    float* a_s = sh + AS_OFF;
    float4* part4f = (float4*)(sh + PART_OFF);
    float* parts2f = sh + PART_OFF;     // scalar partial buffer (stage2; reuses region)
    const int tid  = threadIdx.x;
    const int bid  = blockIdx.x;
    const int lane = tid & 31;
    const int warp = tid >> 5;          // 0..15
    unsigned long long target = 0ULL;

    // ---------------- pack gate weights + biases into global ----------------
    for (int idx = bid * NTHR + tid; idx < 3 * Hz * 640; idx += NBLK * NTHR) {
        int j = idx % 640;
        int k = (idx / 640) % Hz;
        int g = idx / (640 * Hz);
        float v;
        if (j < 512) v = W_hh[(g * Hz + k) * Hz + j];
        else         v = W_ih[(g * Hz + k) * (2 * Dz) + (j - 512)];
        g_wpack[idx] = v;
    }
    for (int k = bid * NTHR + tid; k < Hz; k += NBLK * NTHR) {
        g_bsum[k]      = b_ih[k] + b_hh[k];
        g_bsum[Hz + k] = b_ih[Hz + k] + b_hh[Hz + k];
        g_bin[k]       = b_ih[2 * Hz + k];
        g_bhn[k]       = b_hh[2 * Hz + k];
    }
    // one-shot full-grid barrier
    __syncthreads();
    if (tid == 0) {
        __threadfence();
        atomicAdd(&g_bar_init, 1ULL);
        while (*(volatile unsigned long long*)&g_bar_init < (unsigned long long)NBLK) { }
        __threadfence();
    }
    __syncthreads();

    const int half = bid & 1;
    const int b0   = half * 32;            // batch half base
    const int kb   = bid >> 1;             // k-chunk (8 wide) index, 0..63
    const int wk   = warp & 7;             // k index within chunk
    const int jhalf = warp >> 3;           // 0/1: j-range half
    const int k    = kb * 8 + wk;          // this warp's output unit
    const int row  = tid >> 4;             // 0..31 staging row (= batch within half)
    const int q    = tid & 15;             // staging sub-slot (float4)
    const int bg   = b0 + row;

    // ---------------- stage this CTA's weight slices into smem ----------------
    for (int i4 = tid; i4 < 3840; i4 += NTHR) {          // stage1 gates: 3*8*640 floats
        int j4 = i4 % 160;
        int rem = i4 / 160;          // 0..23
        int w = rem & 7;
        int g = rem >> 3;
        ((float4*)(sh + W1S_OFF))[(w * 3 + g) * 160 + j4] =
            ((const float4*)g_wpack)[(g * Hz + kb * 8 + w) * 160 + j4];
    }
    for (int i4 = tid; i4 < 1024; i4 += NTHR) {          // cb_w1 slice: 8*512 floats
        int j4 = i4 & 127;
        int w = i4 >> 7;
        ((float4*)(sh + W2S_OFF))[w * 128 + j4] =
            __ldg(((const float4*)cb_w1) + (size_t)(kb * 8 + w) * 128 + j4);
    }
    if (tid < 512) {                                     // cb_w2 slice: [d][8]
        int d = tid >> 3, kk = tid & 7;
        sh[W3S_OFF + d * 8 + kk] = __ldg(cb_w2 + (size_t)d * Hz + kb * 8 + kk);
    }

    // zero the h region of smem (h_{-1} = 0); rows [0..128) float4
    {
        float4 z4 = make_float4(0.f, 0.f, 0.f, 0.f);
        float4* dst = (float4*)(sh + row * PITCH);
#pragma unroll
        for (int i = 0; i < 8; i++) dst[i * 16 + q] = z4;
    }
    __syncthreads();

    // warp-uniform smem weight pointers (broadcast LDS in the loop)
    const ulonglong2* wr2 = (const ulonglong2*)(sh + W1S_OFF + (wk * 3 + 0) * 640);
    const ulonglong2* wz2 = (const ulonglong2*)(sh + W1S_OFF + (wk * 3 + 1) * 640);
    const ulonglong2* wn2 = (const ulonglong2*)(sh + W1S_OFF + (wk * 3 + 2) * 640);
    const ulonglong2* w12 = (const ulonglong2*)(sh + W2S_OFF + wk * 512);
    const float bs_r = g_bsum[k];
    const float bs_z = g_bsum[Hz + k];
    const float bi_n = g_bin[k];
    const float bh_n = g_bhn[k];
    const float b1k  = cb_b1[k];

    // stage1 j-split (units of 4 floats): jhalf0 -> [0,80) all h-part;
    // jhalf1 -> [80,128) h-part + [128,160) x|pred-part
    const int jbeg = jhalf ? 80 : 0;
    const int jmid = jhalf ? 128 : 80;

    for (int t = 0; t < Sz; t++) {
        const int pw = t & 1;          // accumulate parity this step
        const int pr = (t + 1) & 1;    // read parity (accumulated at t-1)

        // =========================== Stage 1 ===========================
        {
            // stage x_t into slots [128..144) and pred_{t-1} (+bias) into [144..160)
            float4* dst = (float4*)(sh + row * PITCH);
            const float4* xp = (const float4*)(x + ((size_t)bg * Sz + t) * Dz);
            dst[128 + q] = __ldg(xp + q);
            if (t > 0) {
                const float4* pp = (const float4*)(g_pred[pr] + bg * Dz);
                float4 ba = __ldg((const float4*)(cb_b2 + 4 * q));
                float4 v0 = ldcg4(pp + q);
                v0.x += ba.x; v0.y += ba.y; v0.z += ba.z; v0.w += ba.w;
                dst[144 + q] = v0;
                if (kb == 0) {  // write pred_{t-1} output (includes bias)
                    float4* ob = (float4*)(out_cb + ((size_t)bg * Sz + (t - 1)) * Dz);
                    ob[q] = v0;
                }
            } else {
                dst[144 + q] = make_float4(0.f, 0.f, 0.f, 0.f);
            }
            __syncthreads();

            const ulonglong2* hv2 = (const ulonglong2*)(sh + lane * PITCH);
            u64 ar_a = pk2(0.f, 0.f), ar_b = pk2(0.f, 0.f);
            u64 az_a = pk2(0.f, 0.f), az_b = pk2(0.f, 0.f);
            u64 an_a = pk2(0.f, 0.f), an_b = pk2(0.f, 0.f);  // h-part of n
            u64 ai_a = pk2(0.f, 0.f), ai_b = pk2(0.f, 0.f);  // x|pred-part of n

#pragma unroll 4
            for (int jj = jbeg; jj < jmid; jj++) {   // h part: n goes to gh_n
                ulonglong2 h2 = hv2[jj];
                ulonglong2 w0 = wr2[jj];             // smem broadcast
                ulonglong2 w1v = wz2[jj];
                ulonglong2 w2v = wn2[jj];
                fma2(ar_a, h2.x, w0.x);  fma2(ar_b, h2.y, w0.y);
                fma2(az_a, h2.x, w1v.x); fma2(az_b, h2.y, w1v.y);
                fma2(an_a, h2.x, w2v.x); fma2(an_b, h2.y, w2v.y);
            }
            if (jhalf) {
#pragma unroll 4
                for (int jj = 128; jj < 160; jj++) { // x|pred part: n goes to gi_n
                    ulonglong2 h2 = hv2[jj];
                    ulonglong2 w0 = wr2[jj];
                    ulonglong2 w1v = wz2[jj];
                    ulonglong2 w2v = wn2[jj];
                    fma2(ar_a, h2.x, w0.x);  fma2(ar_b, h2.y, w0.y);
                    fma2(az_a, h2.x, w1v.x); fma2(az_b, h2.y, w1v.y);
                    fma2(ai_a, h2.x, w2v.x); fma2(ai_b, h2.y, w2v.y);
                }
            }

            part4f[warp * 32 + lane] =
                make_float4(red2(ar_a, ar_b), red2(az_a, az_b),
                            red2(an_a, an_b), red2(ai_a, ai_b));
            __syncthreads();

            if (warp < 8) {  // combine partner halves + nonlinearity
                float4 p0 = part4f[warp * 32 + lane];
                float4 p1 = part4f[(warp + 8) * 32 + lane];
                float ar  = bs_r + p0.x + p1.x;
                float az  = bs_z + p0.y + p1.y;
                float ahn = bh_n + p0.z + p1.z;
                float ain = bi_n + p0.w + p1.w;
                float r    = sigmoidf_(ar);
                float z    = sigmoidf_(az);
                float n    = tanhf(ain + r * ahn);
                float hold = sh[lane * PITCH + k];  // h_{t-1}[b0+lane][k]
                float hnew = (1.0f - z) * n + z * hold;
                g_outs[(size_t)t * Bz * Hz + (b0 + lane) * Hz + k] = hnew;
                if (t == Sz - 1) out_hid[(b0 + lane) * Hz + k] = hnew;
            }
        }
        gsync_half(half, target);

        // =========================== Stage 2 (+fused pred) ===========================
        {
            // stage h_new (this also becomes stage1's h for t+1)
            const float* src = g_outs + (size_t)t * Bz * Hz;
            const float4* hp = (const float4*)(src + bg * Hz);
            float4* dst = (float4*)(sh + row * PITCH);
#pragma unroll
            for (int i = 0; i < 8; i++) dst[i * 16 + q] = ldcg4(hp + i * 16 + q);
            // reset the pred buffer that was read this step
            if (tid < 32) g_pred[pr][b0 * Dz + kb * 32 + tid] = 0.0f;
            __syncthreads();

            const ulonglong2* hv2 = (const ulonglong2*)(sh + lane * PITCH);
            u64 ac_a = pk2(0.f, 0.f), ac_b = pk2(0.f, 0.f);
            const int j0 = jhalf * 64;
#pragma unroll 4
            for (int jj = j0; jj < j0 + 64; jj++) {
                ulonglong2 h2 = hv2[jj];
                ulonglong2 w4 = w12[jj];             // smem broadcast
                fma2(ac_a, h2.x, w4.x);
                fma2(ac_b, h2.y, w4.y);
            }
            parts2f[warp * 32 + lane] = red2(ac_a, ac_b);
            __syncthreads();

            if (warp < 8) {
                float acc = b1k + parts2f[warp * 32 + lane] + parts2f[(warp + 8) * 32 + lane];
                acc = fmaxf(acc, 0.0f);
                a_s[warp * 32 + lane] = acc;  // a[k = kb*8+warp][b = lane]
            }
            __syncthreads();

            // fused stage3: partial pred over this CTA's 8 k's, RED into g_pred[pw]
            float av0 = a_s[0 * 32 + lane], av1 = a_s[1 * 32 + lane];
            float av2 = a_s[2 * 32 + lane], av3 = a_s[3 * 32 + lane];
            float av4 = a_s[4 * 32 + lane], av5 = a_s[5 * 32 + lane];
            float av6 = a_s[6 * 32 + lane], av7 = a_s[7 * 32 + lane];
            float* predw = g_pred[pw] + (b0 + lane) * Dz;
#pragma unroll
            for (int d8 = 0; d8 < 4; d8++) {
                int d = warp * 4 + d8;    // 16 warps x 4 = 64 outputs
                float4 wa = *(const float4*)(sh + W3S_OFF + d * 8);      // smem broadcast
                float4 wb = *(const float4*)(sh + W3S_OFF + d * 8 + 4);
                float s = av0 * wa.x;
                s = fmaf(av1, wa.y, s);
                s = fmaf(av2, wa.z, s);
                s = fmaf(av3, wa.w, s);
                s = fmaf(av4, wb.x, s);
                s = fmaf(av5, wb.y, s);
                s = fmaf(av6, wb.z, s);
                s = fmaf(av7, wb.w, s);
                atomicAdd(predw + d, s);
            }
        }
        gsync_half(half, target);
    }

    // final pred output for t = Sz-1
    if (kb == 0) {
        const int prf = (Sz - 1) & 1;
        const float4* pp = (const float4*)(g_pred[prf] + bg * Dz);
        float4 ba = __ldg((const float4*)(cb_b2 + 4 * q));
        float4 v0 = ldcg4(pp + q);
        v0.x += ba.x; v0.y += ba.y; v0.z += ba.z; v0.w += ba.w;
        float4* ob = (float4*)(out_cb + ((size_t)bg * Sz + (Sz - 1)) * Dz);
        ob[q] = v0;
    }
}

// =====================================================================================
// Epilogue 1: ca1 = relu(outs @ fc_w^T + fc_b)   [65536 x 512], K=512
// =====================================================================================
__global__ void __launch_bounds__(256) post1_kernel(
    const float* __restrict__ fc_w, const float* __restrict__ fc_b,
    float* __restrict__ out_ca1)
{
    __shared__ float As[16][64];
    __shared__ float Ws[16][64];
    const int r0 = blockIdx.y * 64;
    const int c0 = blockIdx.x * 64;
    const int tid = threadIdx.x;
    const int tx = tid & 15, ty = tid >> 4;

    float acc[4][4];
#pragma unroll
    for (int i = 0; i < 4; i++)
#pragma unroll
        for (int j = 0; j < 4; j++) acc[i][j] = 0.0f;

    const int li = tid >> 2;
    const int lk = (tid & 3) * 4;

    for (int k0 = 0; k0 < Hz; k0 += 16) {
        float4 av = *(const float4*)(g_outs + (size_t)(r0 + li) * Hz + k0 + lk);
        float4 wv = *(const float4*)(fc_w   + (size_t)(c0 + li) * Hz + k0 + lk);
        As[lk + 0][li] = av.x; As[lk + 1][li] = av.y; As[lk + 2][li] = av.z; As[lk + 3][li] = av.w;
        Ws[lk + 0][li] = wv.x; Ws[lk + 1][li] = wv.y; Ws[lk + 2][li] = wv.z; Ws[lk + 3][li] = wv.w;
        __syncthreads();
#pragma unroll
        for (int kk = 0; kk < 16; kk++) {
            float4 a4 = *(const float4*)(&As[kk][ty * 4]);
            float4 w4 = *(const float4*)(&Ws[kk][tx * 4]);
            acc[0][0] = fmaf(a4.x, w4.x, acc[0][0]); acc[0][1] = fmaf(a4.x, w4.y, acc[0][1]);
            acc[0][2] = fmaf(a4.x, w4.z, acc[0][2]); acc[0][3] = fmaf(a4.x, w4.w, acc[0][3]);
            acc[1][0] = fmaf(a4.y, w4.x, acc[1][0]); acc[1][1] = fmaf(a4.y, w4.y, acc[1][1]);
            acc[1][2] = fmaf(a4.y, w4.z, acc[1][2]); acc[1][3] = fmaf(a4.y, w4.w, acc[1][3]);
            acc[2][0] = fmaf(a4.z, w4.x, acc[2][0]); acc[2][1] = fmaf(a4.z, w4.y, acc[2][1]);
            acc[2][2] = fmaf(a4.z, w4.z, acc[2][2]); acc[2][3] = fmaf(a4.z, w4.w, acc[2][3]);
            acc[3][0] = fmaf(a4.w, w4.x, acc[3][0]); acc[3][1] = fmaf(a4.w, w4.y, acc[3][1]);
            acc[3][2] = fmaf(a4.w, w4.z, acc[3][2]); acc[3][3] = fmaf(a4.w, w4.w, acc[3][3]);
        }
        __syncthreads();
    }

    float4 bias = *(const float4*)(fc_b + c0 + tx * 4);
#pragma unroll
    for (int rr = 0; rr < 4; rr++) {
        int r = r0 + ty * 4 + rr;
        int b = r & 63;       // r = t*64 + b
        int t = r >> 6;
        float4 o;
        o.x = fmaxf(acc[rr][0] + bias.x, 0.0f);
        o.y = fmaxf(acc[rr][1] + bias.y, 0.0f);
        o.z = fmaxf(acc[rr][2] + bias.z, 0.0f);
        o.w = fmaxf(acc[rr][3] + bias.w, 0.0f);
        *(float4*)(out_ca1 + ((size_t)b * Sz + t) * Hz + c0 + tx * 4) = o;
    }
}

// =====================================================================================
// Epilogue 2: q = ca1 @ out_w^T + out_b   [65536 x 16], K=512
// =====================================================================================
__global__ void __launch_bounds__(256) post2_kernel(
    const float* __restrict__ out_w, const float* __restrict__ out_b,
    const float* __restrict__ ca1, float* __restrict__ out_q)
{
    __shared__ float ws[Az * 516];
    const int tid = threadIdx.x;
    for (int f = tid; f < Az * 128; f += 256) {
        int a = f >> 7, jj = f & 127;
        float4 v = *(const float4*)(out_w + (size_t)a * Hz + jj * 4);
        *(float4*)(ws + a * 516 + jj * 4) = v;
    }
    __syncthreads();

    const int rl = tid >> 4, a = tid & 15;
    const int r = blockIdx.x * 16 + rl;
    const float4* cp = (const float4*)(ca1 + (size_t)r * Hz);
    const float4* wp = (const float4*)(ws + a * 516);
    float acc = out_b[a];
#pragma unroll 4
    for (int jj = 0; jj < 128; jj++) {
        float4 c4 = __ldg(cp + jj);
        float4 w4 = wp[jj];
        fma4(acc, c4, w4);
    }
    out_q[(size_t)r * Az + a] = acc;
}

// =====================================================================================
extern "C" void kernel_launch(void* const* d_in, const int* in_sizes, int n_in,
                              void* d_out, int out_size) {
    (void)in_sizes; (void)n_in; (void)out_size;
    const float* x     = (const float*)d_in[0];
    const float* W_ih  = (const float*)d_in[1];
    const float* W_hh  = (const float*)d_in[2];
    const float* b_ih  = (const float*)d_in[3];
    const float* b_hh  = (const float*)d_in[4];
    const float* fc_w  = (const float*)d_in[5];
    const float* fc_b  = (const float*)d_in[6];
    const float* out_w = (const float*)d_in[7];
    const float* out_b = (const float*)d_in[8];
    const float* cb_w1 = (const float*)d_in[9];
    const float* cb_b1 = (const float*)d_in[10];
    const float* cb_w2 = (const float*)d_in[11];
    const float* cb_b2 = (const float*)d_in[12];
    float* out = (float*)d_out;

    cudaFuncSetAttribute(recur_kernel, cudaFuncAttributeMaxDynamicSharedMemorySize, SMEM_BYTES);

    reset_kernel<<<33, 256>>>();
    noop_a_kernel<<<1, 1>>>();   // launch-slot shifters: keep recur at ncu's profiled slot
    noop_b_kernel<<<1, 1>>>();
    recur_kernel<<<NBLK, NTHR, SMEM_BYTES>>>(x, W_ih, W_hh, b_ih, b_hh,
                                             cb_w1, cb_b1, cb_w2, cb_b2,
                                             out + CBOFF, out + HIDOFF);
    post1_kernel<<<dim3(8, 1024), 256>>>(fc_w, fc_b, out + CA1OFF);
    post2_kernel<<<4096, 256>>>(out_w, out_b, out + CA1OFF, out + QOFF);
}

// round 15
// speedup vs baseline: 1.2804x; 1.2804x over previous
#include <cuda_runtime.h>
#include <math.h>

// Problem dims
#define Bz 64
#define Sz 1024
#define Dz 64
#define Hz 512
#define Az 16

// Persistent kernel config
#define NBLK 128
#define NTHR 256
#define PITCH 644                    // smem act row pitch in floats (%32==4)

// smem layout (floats)
#define ACT_OFF 0
#define W1S_OFF (16 * PITCH)                 // gate weights [kl(16)][gate(3)][640] = 30720 f
#define W2S_OFF (W1S_OFF + 3 * 16 * 640)     // cb_w1 slice  [kl(16)][512]          = 8192 f
#define W3S_OFF (W2S_OFF + 16 * 512)         // cb_w2 slice  [d(64)][16]            = 1024 f
#define AS_OFF  (W3S_OFF + 1024)             // a_s[kl(16)][b(16)]                  = 256 f
#define SMEM_FLOATS (AS_OFF + 256)
#define SMEM_BYTES (SMEM_FLOATS * 4)         // 201,984 B (< 227KB/block)

// d_out layout: q [B,S,A] | cb_preds [B,S,D] | hidden [B,H] | ca1_out [B,S,H]
#define QOFF   0
#define CBOFF  (Bz * Sz * Az)
#define HIDOFF (CBOFF + Bz * Sz * Dz)
#define CA1OFF (HIDOFF + Bz * Hz)

// ---------------- device scratch (static __device__ only; no allocs) ----------------
__device__ float g_outs[Sz * Bz * Hz];   // h_t for all t, layout [t][b][j]
__device__ float g_wpack[3 * Hz * 640];  // packed gate weights [gate][k][j]; j: 0..511=h, 512..575=x, 576..639=pred
__device__ float g_bsum[2 * Hz];         // b_ih+b_hh for r,z gates
__device__ float g_bin[Hz];              // b_ih for n gate
__device__ float g_bhn[Hz];              // b_hh for n gate
__device__ float g_pred[2][Bz * Dz];     // parity-double-buffered pred accumulators [b][d]
__device__ unsigned long long g_barq[128];  // per-quarter barrier counters at [q*32] (256B apart)
__device__ unsigned long long g_bar_init;   // one-shot full-grid barrier

__global__ void reset_kernel() {
    int idx = blockIdx.x * blockDim.x + threadIdx.x;
    if (idx < 2 * Bz * Dz) ((float*)g_pred)[idx] = 0.0f;
    if (idx < 128) g_barq[idx] = 0ULL;
    if (idx == 128) g_bar_init = 0ULL;
}

// No-op launch-slot shifters so ncu (-s 5 -c 1) lands on recur_kernel.
__global__ void noop_a_kernel() {}
__global__ void noop_b_kernel() {}

__device__ __forceinline__ float4 ldcg4(const float4* p) { return __ldcg(p); }

// ---------------- packed f32x2 helpers ----------------
typedef unsigned long long u64;

__device__ __forceinline__ u64 pk2(float lo, float hi) {
    u64 r;
    asm("mov.b64 %0, {%1, %2};" : "=l"(r) : "f"(lo), "f"(hi));
    return r;
}
__device__ __forceinline__ void upk2(u64 v, float& lo, float& hi) {
    asm("mov.b64 {%0, %1}, %2;" : "=f"(lo), "=f"(hi) : "l"(v));
}
__device__ __forceinline__ void fma2(u64& acc, u64 a, u64 b) {
    asm("fma.rn.f32x2 %0, %1, %2, %3;" : "=l"(acc) : "l"(a), "l"(b), "l"(acc));
}
__device__ __forceinline__ float red2(u64 a, u64 b) {
    float l0, h0, l1, h1;
    upk2(a, l0, h0); upk2(b, l1, h1);
    return (l0 + h0) + (l1 + h1);
}

// Per-quarter grid barrier (32 CTAs per quarter, all co-resident).
__device__ __forceinline__ void gsync_q(int quarter, unsigned long long& target) {
    __syncthreads();
    if (threadIdx.x == 0) {
        __threadfence();
        target += 32ULL;
        atomicAdd(&g_barq[quarter * 32], 1ULL);
        while (*(volatile unsigned long long*)&g_barq[quarter * 32] < target) { }
        __threadfence();
    }
    __syncthreads();
}

__device__ __forceinline__ void fma4(float& acc, const float4 va, const float4 vb) {
    acc = fmaf(va.x, vb.x, acc);
    acc = fmaf(va.y, vb.y, acc);
    acc = fmaf(va.z, vb.z, acc);
    acc = fmaf(va.w, vb.w, acc);
}

__device__ __forceinline__ float sigmoidf_(float v) { return 1.0f / (1.0f + expf(-v)); }

// =====================================================================================
// Persistent recurrent kernel: batch-quartered 2-k-per-lane tiling.
// 128 CTAs = 4 batch quarters (16 b) x 32 k-chunks (16 k). 256 threads.
// lane = (b:0..15, ksub:0..1); warp handles k = kb*16 + warp*2 + ksub per lane.
// Act LDS dedups to 256B (2 cyc); weight LDS dedups to 32B (1 cyc). Full dot per
// thread -> no partial combine. 4 independent 32-CTA barrier domains.
// =====================================================================================
__global__ void __launch_bounds__(NTHR, 1) recur_kernel(
    const float* __restrict__ x,      // [B,S,D]
    const float* __restrict__ W_ih,   // [3H, 2D]
    const float* __restrict__ W_hh,   // [3H, H]
    const float* __restrict__ b_ih,   // [3H]
    const float* __restrict__ b_hh,   // [3H]
    const float* __restrict__ cb_w1,  // [H,H]
    const float* __restrict__ cb_b1,  // [H]
    const float* __restrict__ cb_w2,  // [D,H]
    const float* __restrict__ cb_b2,  // [D]
    float* __restrict__ out_cb,       // d_out + CBOFF  [B,S,D]
    float* __restrict__ out_hid)      // d_out + HIDOFF [B,H]
{
    extern __shared__ float sh[];
    float* a_s = sh + AS_OFF;
    const int tid  = threadIdx.x;
    const int bid  = blockIdx.x;
    const int lane = tid & 31;
    const int warp = tid >> 5;          // 0..7
    unsigned long long target = 0ULL;

    // ---------------- pack gate weights + biases into global ----------------
    for (int idx = bid * NTHR + tid; idx < 3 * Hz * 640; idx += NBLK * NTHR) {
        int j = idx % 640;
        int k = (idx / 640) % Hz;
        int g = idx / (640 * Hz);
        float v;
        if (j < 512) v = W_hh[(g * Hz + k) * Hz + j];
        else         v = W_ih[(g * Hz + k) * (2 * Dz) + (j - 512)];
        g_wpack[idx] = v;
    }
    for (int k = bid * NTHR + tid; k < Hz; k += NBLK * NTHR) {
        g_bsum[k]      = b_ih[k] + b_hh[k];
        g_bsum[Hz + k] = b_ih[Hz + k] + b_hh[Hz + k];
        g_bin[k]       = b_ih[2 * Hz + k];
        g_bhn[k]       = b_hh[2 * Hz + k];
    }
    // one-shot full-grid barrier (wpack written grid-stride by everyone)
    __syncthreads();
    if (tid == 0) {
        __threadfence();
        atomicAdd(&g_bar_init, 1ULL);
        while (*(volatile unsigned long long*)&g_bar_init < (unsigned long long)NBLK) { }
        __threadfence();
    }
    __syncthreads();

    const int quarter = bid & 3;
    const int b0   = quarter * 16;         // batch quarter base
    const int kb   = bid >> 2;             // k-chunk (16 wide) index, 0..31
    const int b    = lane >> 1;            // 0..15 batch within quarter
    const int ksub = lane & 1;
    const int kl   = warp * 2 + ksub;      // 0..15 k within chunk
    const int k    = kb * 16 + kl;         // global k, 0..511
    const int row  = tid >> 4;             // 0..15 staging row
    const int q    = tid & 15;             // staging sub-slot (float4)
    const int bg   = b0 + row;

    // ---------------- stage this CTA's weight slices into smem ----------------
    for (int i4 = tid; i4 < 7680; i4 += NTHR) {          // stage1 gates: 3*16*640 floats
        int j4 = i4 % 160;
        int rem = i4 / 160;          // 0..47
        int klc = rem & 15;
        int g = rem >> 4;
        ((float4*)(sh + W1S_OFF))[(klc * 3 + g) * 160 + j4] =
            ((const float4*)g_wpack)[(g * Hz + kb * 16 + klc) * 160 + j4];
    }
    for (int i4 = tid; i4 < 2048; i4 += NTHR) {          // cb_w1 slice: 16*512 floats
        int j4 = i4 & 127;
        int klc = i4 >> 7;
        ((float4*)(sh + W2S_OFF))[klc * 128 + j4] =
            __ldg(((const float4*)cb_w1) + (size_t)(kb * 16 + klc) * 128 + j4);
    }
    for (int i = tid; i < 1024; i += NTHR) {             // cb_w2 slice: [d][16]
        int d = i >> 4, kk = i & 15;
        sh[W3S_OFF + d * 16 + kk] = __ldg(cb_w2 + (size_t)d * Hz + kb * 16 + kk);
    }

    // zero the h region of smem (h_{-1} = 0); 16 rows x 128 float4
    {
        float4 z4 = make_float4(0.f, 0.f, 0.f, 0.f);
        float4* dst = (float4*)(sh + row * PITCH);
#pragma unroll
        for (int i = 0; i < 8; i++) dst[i * 16 + q] = z4;
    }
    __syncthreads();

    // per-lane smem weight pointers (2 distinct addrs/warp -> 1-wavefront LDS)
    const ulonglong2* wr2 = (const ulonglong2*)(sh + W1S_OFF + (kl * 3 + 0) * 640);
    const ulonglong2* wz2 = (const ulonglong2*)(sh + W1S_OFF + (kl * 3 + 1) * 640);
    const ulonglong2* wn2 = (const ulonglong2*)(sh + W1S_OFF + (kl * 3 + 2) * 640);
    const ulonglong2* w12 = (const ulonglong2*)(sh + W2S_OFF + kl * 512);
    const float bs_r = g_bsum[k];
    const float bs_z = g_bsum[Hz + k];
    const float bi_n = g_bin[k];
    const float bh_n = g_bhn[k];
    const float b1k  = cb_b1[k];

    for (int t = 0; t < Sz; t++) {
        const int pw = t & 1;          // accumulate parity this step
        const int pr = (t + 1) & 1;    // read parity (accumulated at t-1)

        // =========================== Stage 1 ===========================
        {
            // stage x_t into slots [128..144) and pred_{t-1} (+bias) into [144..160)
            float4* dst = (float4*)(sh + row * PITCH);
            const float4* xp = (const float4*)(x + ((size_t)bg * Sz + t) * Dz);
            dst[128 + q] = __ldg(xp + q);
            if (t > 0) {
                const float4* pp = (const float4*)(g_pred[pr] + bg * Dz);
                float4 ba = __ldg((const float4*)(cb_b2 + 4 * q));
                float4 v0 = ldcg4(pp + q);
                v0.x += ba.x; v0.y += ba.y; v0.z += ba.z; v0.w += ba.w;
                dst[144 + q] = v0;
                if (kb == 0) {  // write pred_{t-1} output (includes bias)
                    float4* ob = (float4*)(out_cb + ((size_t)bg * Sz + (t - 1)) * Dz);
                    ob[q] = v0;
                }
            } else {
                dst[144 + q] = make_float4(0.f, 0.f, 0.f, 0.f);
            }
            __syncthreads();

            const ulonglong2* hv2 = (const ulonglong2*)(sh + b * PITCH);
            u64 ar_a = pk2(bs_r, 0.f), ar_b = pk2(0.f, 0.f);
            u64 az_a = pk2(bs_z, 0.f), az_b = pk2(0.f, 0.f);
            u64 an_a = pk2(bh_n, 0.f), an_b = pk2(0.f, 0.f);  // h-part of n
            u64 ai_a = pk2(bi_n, 0.f), ai_b = pk2(0.f, 0.f);  // x|pred-part of n

#pragma unroll 4
            for (int jj = 0; jj < 128; jj++) {   // h part: n goes to gh_n
                ulonglong2 h2 = hv2[jj];
                ulonglong2 w0 = wr2[jj];
                ulonglong2 w1v = wz2[jj];
                ulonglong2 w2v = wn2[jj];
                fma2(ar_a, h2.x, w0.x);  fma2(ar_b, h2.y, w0.y);
                fma2(az_a, h2.x, w1v.x); fma2(az_b, h2.y, w1v.y);
                fma2(an_a, h2.x, w2v.x); fma2(an_b, h2.y, w2v.y);
            }
#pragma unroll 4
            for (int jj = 128; jj < 160; jj++) { // x|pred part: n goes to gi_n
                ulonglong2 h2 = hv2[jj];
                ulonglong2 w0 = wr2[jj];
                ulonglong2 w1v = wz2[jj];
                ulonglong2 w2v = wn2[jj];
                fma2(ar_a, h2.x, w0.x);  fma2(ar_b, h2.y, w0.y);
                fma2(az_a, h2.x, w1v.x); fma2(az_b, h2.y, w1v.y);
                fma2(ai_a, h2.x, w2v.x); fma2(ai_b, h2.y, w2v.y);
            }

            float ar  = red2(ar_a, ar_b);
            float az  = red2(az_a, az_b);
            float ahn = red2(an_a, an_b);
            float ain = red2(ai_a, ai_b);

            float r    = sigmoidf_(ar);
            float z    = sigmoidf_(az);
            float n    = tanhf(ain + r * ahn);
            float hold = sh[b * PITCH + k];  // h_{t-1}[b0+b][k]
            float hnew = (1.0f - z) * n + z * hold;
            g_outs[(size_t)t * Bz * Hz + (b0 + b) * Hz + k] = hnew;
            if (t == Sz - 1) out_hid[(b0 + b) * Hz + k] = hnew;
        }
        gsync_q(quarter, target);

        // =========================== Stage 2 (+fused pred) ===========================
        {
            // stage h_new (this also becomes stage1's h for t+1)
            const float* src = g_outs + (size_t)t * Bz * Hz;
            const float4* hp = (const float4*)(src + bg * Hz);
            float4* dst = (float4*)(sh + row * PITCH);
#pragma unroll
            for (int i = 0; i < 8; i++) dst[i * 16 + q] = ldcg4(hp + i * 16 + q);
            // reset the pred buffer that was read this step (quarter region)
            if (tid < 32) g_pred[pr][b0 * Dz + kb * 32 + tid] = 0.0f;
            __syncthreads();

            const ulonglong2* hv2 = (const ulonglong2*)(sh + b * PITCH);
            u64 ac_a = pk2(b1k, 0.f), ac_b = pk2(0.f, 0.f);
#pragma unroll 4
            for (int jj = 0; jj < 128; jj++) {
                ulonglong2 h2 = hv2[jj];
                ulonglong2 w4 = w12[jj];
                fma2(ac_a, h2.x, w4.x);
                fma2(ac_b, h2.y, w4.y);
            }
            float acc = red2(ac_a, ac_b);
            acc = fmaxf(acc, 0.0f);
            a_s[kl * 16 + b] = acc;  // a[kl][b]
            __syncthreads();

            // fused stage3: partial pred over this CTA's 16 k's, RED into g_pred[pw]
            float av[16];
#pragma unroll
            for (int kk = 0; kk < 16; kk++) av[kk] = a_s[kk * 16 + b];
            const int dh = lane & 1;
            float* predw = g_pred[pw] + (b0 + b) * Dz;
#pragma unroll
            for (int d8 = 0; d8 < 4; d8++) {
                int d = warp * 8 + dh * 4 + d8;   // 8 warps x 2 x 4 = 64 outputs
                const float* w3 = sh + W3S_OFF + d * 16;
                float s = av[0] * w3[0];
#pragma unroll
                for (int kk = 1; kk < 16; kk++) s = fmaf(av[kk], w3[kk], s);
                atomicAdd(predw + d, s);
            }
        }
        gsync_q(quarter, target);
    }

    // final pred output for t = Sz-1
    if (kb == 0) {
        const int prf = (Sz - 1) & 1;
        const float4* pp = (const float4*)(g_pred[prf] + bg * Dz);
        float4 ba = __ldg((const float4*)(cb_b2 + 4 * q));
        float4 v0 = ldcg4(pp + q);
        v0.x += ba.x; v0.y += ba.y; v0.z += ba.z; v0.w += ba.w;
        float4* ob = (float4*)(out_cb + ((size_t)bg * Sz + (Sz - 1)) * Dz);
        ob[q] = v0;
    }
}

// =====================================================================================
// Epilogue 1: ca1 = relu(outs @ fc_w^T + fc_b)   [65536 x 512], K=512
// =====================================================================================
__global__ void __launch_bounds__(256) post1_kernel(
    const float* __restrict__ fc_w, const float* __restrict__ fc_b,
    float* __restrict__ out_ca1)
{
    __shared__ float As[16][64];
    __shared__ float Ws[16][64];
    const int r0 = blockIdx.y * 64;
    const int c0 = blockIdx.x * 64;
    const int tid = threadIdx.x;
    const int tx = tid & 15, ty = tid >> 4;

    float acc[4][4];
#pragma unroll
    for (int i = 0; i < 4; i++)
#pragma unroll
        for (int j = 0; j < 4; j++) acc[i][j] = 0.0f;

    const int li = tid >> 2;
    const int lk = (tid & 3) * 4;

    for (int k0 = 0; k0 < Hz; k0 += 16) {
        float4 av = *(const float4*)(g_outs + (size_t)(r0 + li) * Hz + k0 + lk);
        float4 wv = *(const float4*)(fc_w   + (size_t)(c0 + li) * Hz + k0 + lk);
        As[lk + 0][li] = av.x; As[lk + 1][li] = av.y; As[lk + 2][li] = av.z; As[lk + 3][li] = av.w;
        Ws[lk + 0][li] = wv.x; Ws[lk + 1][li] = wv.y; Ws[lk + 2][li] = wv.z; Ws[lk + 3][li] = wv.w;
        __syncthreads();
#pragma unroll
        for (int kk = 0; kk < 16; kk++) {
            float4 a4 = *(const float4*)(&As[kk][ty * 4]);
            float4 w4 = *(const float4*)(&Ws[kk][tx * 4]);
            acc[0][0] = fmaf(a4.x, w4.x, acc[0][0]); acc[0][1] = fmaf(a4.x, w4.y, acc[0][1]);
            acc[0][2] = fmaf(a4.x, w4.z, acc[0][2]); acc[0][3] = fmaf(a4.x, w4.w, acc[0][3]);
            acc[1][0] = fmaf(a4.y, w4.x, acc[1][0]); acc[1][1] = fmaf(a4.y, w4.y, acc[1][1]);
            acc[1][2] = fmaf(a4.y, w4.z, acc[1][2]); acc[1][3] = fmaf(a4.y, w4.w, acc[1][3]);
            acc[2][0] = fmaf(a4.z, w4.x, acc[2][0]); acc[2][1] = fmaf(a4.z, w4.y, acc[2][1]);
            acc[2][2] = fmaf(a4.z, w4.z, acc[2][2]); acc[2][3] = fmaf(a4.z, w4.w, acc[2][3]);
            acc[3][0] = fmaf(a4.w, w4.x, acc[3][0]); acc[3][1] = fmaf(a4.w, w4.y, acc[3][1]);
            acc[3][2] = fmaf(a4.w, w4.z, acc[3][2]); acc[3][3] = fmaf(a4.w, w4.w, acc[3][3]);
        }
        __syncthreads();
    }

    float4 bias = *(const float4*)(fc_b + c0 + tx * 4);
#pragma unroll
    for (int rr = 0; rr < 4; rr++) {
        int r = r0 + ty * 4 + rr;
        int b = r & 63;       // r = t*64 + b
        int t = r >> 6;
        float4 o;
        o.x = fmaxf(acc[rr][0] + bias.x, 0.0f);
        o.y = fmaxf(acc[rr][1] + bias.y, 0.0f);
        o.z = fmaxf(acc[rr][2] + bias.z, 0.0f);
        o.w = fmaxf(acc[rr][3] + bias.w, 0.0f);
        *(float4*)(out_ca1 + ((size_t)b * Sz + t) * Hz + c0 + tx * 4) = o;
    }
}

// =====================================================================================
// Epilogue 2: q = ca1 @ out_w^T + out_b   [65536 x 16], K=512
// =====================================================================================
__global__ void __launch_bounds__(256) post2_kernel(
    const float* __restrict__ out_w, const float* __restrict__ out_b,
    const float* __restrict__ ca1, float* __restrict__ out_q)
{
    __shared__ float ws[Az * 516];
    const int tid = threadIdx.x;
    for (int f = tid; f < Az * 128; f += 256) {
        int a = f >> 7, jj = f & 127;
        float4 v = *(const float4*)(out_w + (size_t)a * Hz + jj * 4);
        *(float4*)(ws + a * 516 + jj * 4) = v;
    }
    __syncthreads();

    const int rl = tid >> 4, a = tid & 15;
    const int r = blockIdx.x * 16 + rl;
    const float4* cp = (const float4*)(ca1 + (size_t)r * Hz);
    const float4* wp = (const float4*)(ws + a * 516);
    float acc = out_b[a];
#pragma unroll 4
    for (int jj = 0; jj < 128; jj++) {
        float4 c4 = __ldg(cp + jj);
        float4 w4 = wp[jj];
        fma4(acc, c4, w4);
    }
    out_q[(size_t)r * Az + a] = acc;
}

// =====================================================================================
extern "C" void kernel_launch(void* const* d_in, const int* in_sizes, int n_in,
                              void* d_out, int out_size) {
    (void)in_sizes; (void)n_in; (void)out_size;
    const float* x     = (const float*)d_in[0];
    const float* W_ih  = (const float*)d_in[1];
    const float* W_hh  = (const float*)d_in[2];
    const float* b_ih  = (const float*)d_in[3];
    const float* b_hh  = (const float*)d_in[4];
    const float* fc_w  = (const float*)d_in[5];
    const float* fc_b  = (const float*)d_in[6];
    const float* out_w = (const float*)d_in[7];
    const float* out_b = (const float*)d_in[8];
    const float* cb_w1 = (const float*)d_in[9];
    const float* cb_b1 = (const float*)d_in[10];
    const float* cb_w2 = (const float*)d_in[11];
    const float* cb_b2 = (const float*)d_in[12];
    float* out = (float*)d_out;

    cudaFuncSetAttribute(recur_kernel, cudaFuncAttributeMaxDynamicSharedMemorySize, SMEM_BYTES);

    reset_kernel<<<33, 256>>>();
    noop_a_kernel<<<1, 1>>>();   // launch-slot shifters: keep recur at ncu's profiled slot
    noop_b_kernel<<<1, 1>>>();
    recur_kernel<<<NBLK, NTHR, SMEM_BYTES>>>(x, W_ih, W_hh, b_ih, b_hh,
                                             cb_w1, cb_b1, cb_w2, cb_b2,
                                             out + CBOFF, out + HIDOFF);
    post1_kernel<<<dim3(8, 1024), 256>>>(fc_w, fc_b, out + CA1OFF);
    post2_kernel<<<4096, 256>>>(out_w, out_b, out + CA1OFF, out + QOFF);
}